// round 8
// baseline (speedup 1.0000x reference)
#include <cuda_runtime.h>

// DigitCaps dynamic routing, fused. B=64, R=6912, I=8, C=10, O=16, 3 iters.
//
// Loop inversion: CTA owns a 24-r block and loops over all 10 c internally.
// x tile (48 KB) is staged into smem ONCE per CTA; W tiles (12 KB per c)
// stream through a cp.async double buffer. The inner loop reads only smem.
//   k_pass<0>: p=W^T x; acc += p;                 last CTA: out0=squash
//   k_pass<1>: w=exp(p.out0); acc += w*p;         last CTA: out1=squash
//   k_pass<2>: w=exp(p.(out0+out1)); acc += w*p;  last CTA: squash->d_out
// logits never materialized (logit2 = p.(out0+out1)). Replay-clean state.

#define R_DIM 6912
#define B_DIM 64
#define C_DIM 10
#define R_BLK 24
#define NCTAS (R_DIM / R_BLK)             // 288

// dynamic smem layout (bytes)
#define SX_OFF   0                        // float4[48][64]  = 49152
#define SW_OFF   49152                    // float [2][3072] = 24576
#define SP_OFF   (49152 + 24576)          // float [4][64][16] = 16384
#define SWW_OFF  (SP_OFF + 16384)         // float [4][64] = 1024
#define SMEM_TOTAL (SWW_OFF + 1024)       // 91136

typedef unsigned long long u64;

__device__ __align__(16) float g_xT[R_DIM * 2 * B_DIM * 4];   // [r*2+h][b] float4
__device__ __align__(16) float g_acc[C_DIM * B_DIM * 16];
__device__ __align__(16) float g_accw[C_DIM * B_DIM];
__device__ __align__(16) float g_out[2][C_DIM * B_DIM * 16];
__device__ unsigned g_ctr = 0;

__device__ __forceinline__ u64 pack2(float lo, float hi) {
    u64 r; asm("mov.b64 %0, {%1, %2};" : "=l"(r) : "f"(lo), "f"(hi)); return r;
}
__device__ __forceinline__ void unpack2(u64 v, float& lo, float& hi) {
    asm("mov.b64 {%0, %1}, %2;" : "=f"(lo), "=f"(hi) : "l"(v));
}
__device__ __forceinline__ u64 fma2(u64 a, u64 b, u64 c) {
    u64 d; asm("fma.rn.f32x2 %0, %1, %2, %3;" : "=l"(d) : "l"(a), "l"(b), "l"(c)); return d;
}
__device__ __forceinline__ u64 add2(u64 a, u64 b) {
    u64 d; asm("add.rn.f32x2 %0, %1, %2;" : "=l"(d) : "l"(a), "l"(b)); return d;
}
__device__ __forceinline__ unsigned smem_u32(const void* p) {
    return (unsigned)__cvta_generic_to_shared(p);
}
__device__ __forceinline__ void cp_async16(unsigned saddr, const void* g) {
    asm volatile("cp.async.cg.shared.global [%0], [%1], 16;" :: "r"(saddr), "l"(g));
}

// x as float4 matrix [64][13824] -> [13824][64]
__global__ void k_transpose(const float4* __restrict__ x4) {
    __shared__ float4 tile[32][33];
    const int jb = blockIdx.x * 32;
    const int bb = blockIdx.y * 32;
    const int tx = threadIdx.x, ty = threadIdx.y;   // 32 x 8
    #pragma unroll
    for (int k = 0; k < 32; k += 8)
        tile[ty + k][tx] = x4[(size_t)(bb + ty + k) * (R_DIM * 2) + jb + tx];
    __syncthreads();
    float4* out4 = reinterpret_cast<float4*>(g_xT);
    #pragma unroll
    for (int k = 0; k < 32; k += 8)
        out4[(size_t)(jb + ty + k) * B_DIM + bb + tx] = tile[tx][ty + k];
}

// MODE 0: uniform; 1: w=exp(p.out0); 2: w=exp(p.(out0+out1))
template <int MODE>
__global__ void __launch_bounds__(256, 2)
k_pass(const float* __restrict__ Wg, float* __restrict__ dout) {
    extern __shared__ __align__(16) char smem[];
    float4* sx   = reinterpret_cast<float4*>(smem + SX_OFF);    // [rl*2+h][b]
    float*  sWb  = reinterpret_cast<float*>(smem + SW_OFF);     // 2 x 3072 floats
    float*  sP   = reinterpret_cast<float*>(smem + SP_OFF);     // [4][64][16]
    float*  sWw  = reinterpret_cast<float*>(smem + SWW_OFF);    // [4][64]
    __shared__ unsigned s_rank;

    const int rblock = blockIdx.x * R_BLK;
    const int tid    = threadIdx.x;
    const int warp   = tid >> 5;
    const int lane   = tid & 31;
    const int rgroup = warp >> 1;                 // 0..3, each owns 6 r
    const int bhalf  = warp & 1;
    const int oq     = lane >> 3;                 // o-quarter 0..3
    const int bq     = lane & 7;
    const int bbase  = bhalf * 32 + bq;           // owns bbase + {0,8,16,24}

    // ---- stage x tile (48 KB, contiguous in g_xT) ----
    {
        const float4* gx = reinterpret_cast<const float4*>(g_xT) + (size_t)rblock * 2 * B_DIM;
        unsigned dst = smem_u32(sx);
        #pragma unroll
        for (int s = 0; s < 12; s++)
            cp_async16(dst + (tid + s * 256) * 16, gx + tid + s * 256);
        asm volatile("cp.async.commit_group;");
    }
    // ---- prefetch W tiles for c=0, c=1 (12 KB each, contiguous) ----
    #pragma unroll
    for (int pc = 0; pc < 2; pc++) {
        const char* src = reinterpret_cast<const char*>(Wg + ((size_t)pc * R_DIM + rblock) * 128);
        unsigned dst = smem_u32(sWb + pc * 3072);
        #pragma unroll
        for (int s = 0; s < 3; s++)
            cp_async16(dst + (tid + s * 256) * 16, src + (tid + s * 256) * 16);
        asm volatile("cp.async.commit_group;");
    }

    #pragma unroll 1
    for (int c = 0; c < C_DIM; c++) {
        asm volatile("cp.async.wait_group 1;");   // x + W[c] landed
        __syncthreads();                          // (A) also orders prev fold vs sred writes

        // out vectors for this c (4 b x o-quarter)
        u64 ov[4][2];
        if (MODE != 0) {
            #pragma unroll
            for (int j = 0; j < 4; j++) {
                const u64* p0 = reinterpret_cast<const u64*>(
                    g_out[0] + (c * B_DIM + bbase + j * 8) * 16 + oq * 4);
                ov[j][0] = p0[0]; ov[j][1] = p0[1];
                if (MODE == 2) {
                    const u64* p1 = reinterpret_cast<const u64*>(
                        g_out[1] + (c * B_DIM + bbase + j * 8) * 16 + oq * 4);
                    ov[j][0] = add2(ov[j][0], p1[0]);
                    ov[j][1] = add2(ov[j][1], p1[1]);
                }
            }
        }

        const float* sWc = sWb + (c & 1) * 3072;
        u64 acc[4][2];
        #pragma unroll
        for (int j = 0; j < 4; j++) { acc[j][0] = 0ull; acc[j][1] = 0ull; }
        float accw[4] = {0.0f, 0.0f, 0.0f, 0.0f};

        #pragma unroll 1
        for (int rr = 0; rr < 6; rr++) {
            const int rl = rgroup * 6 + rr;

            u64 p[4][2];
            #pragma unroll
            for (int j = 0; j < 4; j++) { p[j][0] = 0ull; p[j][1] = 0ull; }

            #pragma unroll
            for (int h = 0; h < 2; h++) {
                float4 xv[4];
                #pragma unroll
                for (int j = 0; j < 4; j++)
                    xv[j] = sx[(rl * 2 + h) * B_DIM + bbase + j * 8];
                #pragma unroll
                for (int ii = 0; ii < 4; ii++) {
                    const int i = h * 4 + ii;
                    ulonglong2 wv = *reinterpret_cast<const ulonglong2*>(
                        sWc + rl * 128 + i * 16 + oq * 4);
                    #pragma unroll
                    for (int j = 0; j < 4; j++) {
                        float xs = (ii == 0) ? xv[j].x : (ii == 1) ? xv[j].y
                                 : (ii == 2) ? xv[j].z : xv[j].w;
                        u64 xx = pack2(xs, xs);
                        p[j][0] = fma2(wv.x, xx, p[j][0]);
                        p[j][1] = fma2(wv.y, xx, p[j][1]);
                    }
                }
            }

            if (MODE == 0) {
                #pragma unroll
                for (int j = 0; j < 4; j++) {
                    acc[j][0] = add2(acc[j][0], p[j][0]);
                    acc[j][1] = add2(acc[j][1], p[j][1]);
                }
            } else {
                #pragma unroll
                for (int j = 0; j < 4; j++) {
                    u64 d = fma2(p[j][0], ov[j][0], 0ull);
                    d = fma2(p[j][1], ov[j][1], d);
                    float lo, hi; unpack2(d, lo, hi);
                    float del = lo + hi;
                    del += __shfl_xor_sync(0xffffffffu, del, 8);
                    del += __shfl_xor_sync(0xffffffffu, del, 16);
                    del = fminf(del, 70.0f);
                    float w = __expf(del);
                    accw[j] += w;
                    u64 w2 = pack2(w, w);
                    acc[j][0] = fma2(p[j][0], w2, acc[j][0]);
                    acc[j][1] = fma2(p[j][1], w2, acc[j][1]);
                }
            }
        }

        __syncthreads();      // (B) done reading sW[c&1]; safe to refill below

        // prefetch W tile c+2 into the buffer just freed
        if (c + 2 < C_DIM) {
            const char* src = reinterpret_cast<const char*>(
                Wg + ((size_t)(c + 2) * R_DIM + rblock) * 128);
            unsigned dst = smem_u32(sWb + (c & 1) * 3072);
            #pragma unroll
            for (int s = 0; s < 3; s++)
                cp_async16(dst + (tid + s * 256) * 16, src + (tid + s * 256) * 16);
        }
        asm volatile("cp.async.commit_group;");   // keep group count in lockstep

        // write partials (disjoint per warp: [rgroup][b-half])
        #pragma unroll
        for (int j = 0; j < 4; j++) {
            float a0, a1, a2, a3;
            unpack2(acc[j][0], a0, a1);
            unpack2(acc[j][1], a2, a3);
            *reinterpret_cast<float4*>(
                sP + ((rgroup * B_DIM + bbase + j * 8) * 16) + oq * 4) =
                make_float4(a0, a1, a2, a3);
            if (MODE != 0 && oq == 0) sWw[rgroup * B_DIM + bbase + j * 8] = accw[j];
        }
        __syncthreads();      // (C) partials visible

        // fold 4 rgroups -> red.global (result unused -> REDG)
        for (int idx = tid; idx < B_DIM * 16; idx += 256) {
            float v = sP[idx] + sP[1024 + idx] + sP[2048 + idx] + sP[3072 + idx];
            atomicAdd(&g_acc[c * (B_DIM * 16) + idx], v);
        }
        if (MODE != 0 && tid < B_DIM) {
            float v = sWw[tid] + sWw[B_DIM + tid] + sWw[2 * B_DIM + tid] + sWw[3 * B_DIM + tid];
            atomicAdd(&g_accw[c * B_DIM + tid], v);
        }
    }

    // ---- last CTA: squash inline ----
    __threadfence();
    if (tid == 0) s_rank = atomicAdd(&g_ctr, 1);
    __syncthreads();
    if (s_rank == NCTAS - 1) {
        for (int pair = tid; pair < C_DIM * B_DIM; pair += 256) {
            const float* a = g_acc + pair * 16;
            float invw = (MODE == 0) ? (1.0f / (float)R_DIM) : (1.0f / __ldcg(&g_accw[pair]));
            float s[16], sq = 0.0f;
            #pragma unroll
            for (int o = 0; o < 16; o++) { s[o] = __ldcg(a + o) * invw; sq += s[o] * s[o]; }
            float coef = sq / ((1.0f + sq) * sqrtf(sq));
            float* dst = (MODE == 2) ? (dout + pair * 16) : (g_out[MODE] + pair * 16);
            #pragma unroll
            for (int o = 0; o < 16; o++) dst[o] = coef * s[o];
        }
        __syncthreads();
        for (int idx = tid; idx < C_DIM * B_DIM * 16; idx += 256) g_acc[idx] = 0.0f;
        for (int idx = tid; idx < C_DIM * B_DIM; idx += 256) g_accw[idx] = 0.0f;
        if (tid == 0) g_ctr = 0;
    }
}

extern "C" void kernel_launch(void* const* d_in, const int* in_sizes, int n_in,
                              void* d_out, int out_size) {
    const float* x = (const float*)d_in[0];          // [64, 6912, 8]
    const float* W = (const float*)d_in[1];          // [10, 6912, 8, 16]
    float* out = (float*)d_out;                      // [10, 64, 1, 1, 16]

    static bool attr_done = false;
    if (!attr_done) {
        cudaFuncSetAttribute(k_pass<0>, cudaFuncAttributeMaxDynamicSharedMemorySize, SMEM_TOTAL);
        cudaFuncSetAttribute(k_pass<1>, cudaFuncAttributeMaxDynamicSharedMemorySize, SMEM_TOTAL);
        cudaFuncSetAttribute(k_pass<2>, cudaFuncAttributeMaxDynamicSharedMemorySize, SMEM_TOTAL);
        attr_done = true;
    }

    dim3 tgrid(R_DIM * 2 / 32, B_DIM / 32);          // (432, 2)
    k_transpose<<<tgrid, dim3(32, 8)>>>(reinterpret_cast<const float4*>(x));

    k_pass<0><<<NCTAS, 256, SMEM_TOTAL>>>(W, nullptr);
    k_pass<1><<<NCTAS, 256, SMEM_TOTAL>>>(W, nullptr);
    k_pass<2><<<NCTAS, 256, SMEM_TOTAL>>>(W, out);
}

// round 9
// speedup vs baseline: 1.3158x; 1.3158x over previous
#include <cuda_runtime.h>

// DigitCaps dynamic routing, fused. B=64, R=6912, I=8, C=10, O=16, 3 iters.
//
//   k_transpose : x[B,R,I] -> xT[j=r*2+h][b] (float4 transposed)
//   k_pass<0>   : p=W^T x; acc += p;                 last CTA: out0=squash
//   k_pass<1>   : w=exp(p.out0); acc += w*p;         last CTA: out1=squash
//   k_pass<2>   : w=exp(p.(out0+out1)); acc += w*p;  last CTA: squash->d_out
//
// R4 layout (thread owns (b,b+16) x 8-o half; W via smem broadcast LDS;
// dot joined with shfl_xor(16)) + register double-buffer prefetch of the
// next k-step's x float4s so the L2 load latency overlaps the 64 fma2 of
// the current step. 192-thread CTAs, 3/SM (96 regs), R_BLK=48.
// logits never materialized. Replay-clean state.

#define R_DIM 6912
#define B_DIM 64
#define C_DIM 10
#define R_BLK 48
#define NCTAS ((R_DIM / R_BLK) * C_DIM)   // 1440

typedef unsigned long long u64;

// +2 r of slack so the k=15 prefetch of the last CTA block stays in bounds
__device__ __align__(16) float g_xT[(R_DIM + 2) * 2 * B_DIM * 4];
__device__ __align__(16) float g_acc[C_DIM * B_DIM * 16];
__device__ __align__(16) float g_accw[C_DIM * B_DIM];
__device__ __align__(16) float g_out[2][C_DIM * B_DIM * 16];
__device__ unsigned g_ctr = 0;

__device__ __forceinline__ u64 pack2(float lo, float hi) {
    u64 r; asm("mov.b64 %0, {%1, %2};" : "=l"(r) : "f"(lo), "f"(hi)); return r;
}
__device__ __forceinline__ void unpack2(u64 v, float& lo, float& hi) {
    asm("mov.b64 {%0, %1}, %2;" : "=f"(lo), "=f"(hi) : "l"(v));
}
__device__ __forceinline__ u64 fma2(u64 a, u64 b, u64 c) {
    u64 d; asm("fma.rn.f32x2 %0, %1, %2, %3;" : "=l"(d) : "l"(a), "l"(b), "l"(c)); return d;
}
__device__ __forceinline__ u64 add2(u64 a, u64 b) {
    u64 d; asm("add.rn.f32x2 %0, %1, %2;" : "=l"(d) : "l"(a), "l"(b)); return d;
}
__device__ __forceinline__ unsigned smem_u32(const void* p) {
    return (unsigned)__cvta_generic_to_shared(p);
}
__device__ __forceinline__ void cp_async16(unsigned saddr, const void* g) {
    asm volatile("cp.async.cg.shared.global [%0], [%1], 16;" :: "r"(saddr), "l"(g));
}

// x as float4 matrix [64][13824] -> [13824][64]
__global__ void k_transpose(const float4* __restrict__ x4) {
    __shared__ float4 tile[32][33];
    const int jb = blockIdx.x * 32;
    const int bb = blockIdx.y * 32;
    const int tx = threadIdx.x, ty = threadIdx.y;   // 32 x 8
    #pragma unroll
    for (int k = 0; k < 32; k += 8)
        tile[ty + k][tx] = x4[(size_t)(bb + ty + k) * (R_DIM * 2) + jb + tx];
    __syncthreads();
    float4* out4 = reinterpret_cast<float4*>(g_xT);
    #pragma unroll
    for (int k = 0; k < 32; k += 8)
        out4[(size_t)(jb + ty + k) * B_DIM + bb + tx] = tile[tx][ty + k];
}

// MODE 0: uniform; 1: w=exp(p.out0); 2: w=exp(p.(out0+out1))
template <int MODE>
__global__ void __launch_bounds__(192, 3)
k_pass(const float* __restrict__ Wg, float* __restrict__ dout) {
    const int c      = blockIdx.y;
    const int rblock = blockIdx.x * R_BLK;
    const int tid    = threadIdx.x;
    const int warp   = tid >> 5;                  // 0..5
    const int lane   = tid & 31;
    const int rgroup = warp >> 1;                 // 0..2, each covers 16 r
    const int bhalf  = warp & 1;
    const int oh     = lane >> 4;                 // o-half: 0 or 1
    const int bq     = lane & 15;
    const int b0     = bhalf * 32 + bq;           // owns b0 and b0+16
    const int b1     = b0 + 16;

    __shared__ __align__(16) float sW[R_BLK * 128];   // 24 KB
    __shared__ float sredP[3][B_DIM][16];             // 12 KB
    __shared__ float sredW[3][B_DIM];
    __shared__ unsigned s_rank;

    // --- stage W tile (contiguous 24 KB) ---
    {
        const char* src = reinterpret_cast<const char*>(Wg + ((size_t)c * R_DIM + rblock) * 128);
        unsigned dst = smem_u32(sW);
        #pragma unroll
        for (int s = 0; s < 8; s++)
            cp_async16(dst + (tid + s * 192) * 16, src + (size_t)(tid + s * 192) * 16);
        asm volatile("cp.async.commit_group;");
    }

    // out-half vectors for b0, b1 (constant over r) — load while W flies
    u64 ov0[4], ov1[4];
    if (MODE != 0) {
        const u64* p00 = reinterpret_cast<const u64*>(g_out[0] + (c * B_DIM + b0) * 16 + oh * 8);
        const u64* p01 = reinterpret_cast<const u64*>(g_out[0] + (c * B_DIM + b1) * 16 + oh * 8);
        #pragma unroll
        for (int t = 0; t < 4; t++) { ov0[t] = p00[t]; ov1[t] = p01[t]; }
        if (MODE == 2) {
            const u64* p10 = reinterpret_cast<const u64*>(g_out[1] + (c * B_DIM + b0) * 16 + oh * 8);
            const u64* p11 = reinterpret_cast<const u64*>(g_out[1] + (c * B_DIM + b1) * 16 + oh * 8);
            #pragma unroll
            for (int t = 0; t < 4; t++) { ov0[t] = add2(ov0[t], p10[t]); ov1[t] = add2(ov1[t], p11[t]); }
        }
    }

    u64 acc0[4], acc1[4];
    #pragma unroll
    for (int t = 0; t < 4; t++) { acc0[t] = 0ull; acc1[t] = 0ull; }
    float accw0 = 0.0f, accw1 = 0.0f;

    // x base for this warp's 16 r
    const float4* xb4 = reinterpret_cast<const float4*>(g_xT)
                      + (size_t)(rblock + rgroup * 16) * 2 * B_DIM;

    // prefetch k=0 x (4 float4) — overlaps the W-staging wait
    float4 pa0 = xb4[b0], pb0 = xb4[B_DIM + b0];
    float4 pa1 = xb4[b1], pb1 = xb4[B_DIM + b1];

    asm volatile("cp.async.wait_group 0;");
    __syncthreads();

    #pragma unroll 2
    for (int k = 0; k < 16; k++) {
        // consume prefetched x, immediately issue next step's loads
        float4 xa0 = pa0, xb0_ = pb0, xa1 = pa1, xb1_ = pb1;
        {
            const float4* nx = xb4 + (size_t)(k + 1) * 2 * B_DIM;  // padded: safe at k=15
            pa0 = nx[b0]; pb0 = nx[B_DIM + b0];
            pa1 = nx[b1]; pb1 = nx[B_DIM + b1];
        }
        const float xf0[8] = {xa0.x, xa0.y, xa0.z, xa0.w, xb0_.x, xb0_.y, xb0_.z, xb0_.w};
        const float xf1[8] = {xa1.x, xa1.y, xa1.z, xa1.w, xb1_.x, xb1_.y, xb1_.z, xb1_.w};

        const int rl = rgroup * 16 + k;
        const ulonglong2* wp = reinterpret_cast<const ulonglong2*>(sW + rl * 128 + oh * 8);

        u64 p0[4], p1[4];
        #pragma unroll
        for (int t = 0; t < 4; t++) { p0[t] = 0ull; p1[t] = 0ull; }

        #pragma unroll
        for (int i = 0; i < 8; i++) {
            ulonglong2 wA = wp[i * 4 + 0];   // o-half floats 0..3
            ulonglong2 wB = wp[i * 4 + 1];   // o-half floats 4..7
            u64 xx0 = pack2(xf0[i], xf0[i]);
            u64 xx1 = pack2(xf1[i], xf1[i]);
            p0[0] = fma2(wA.x, xx0, p0[0]); p0[1] = fma2(wA.y, xx0, p0[1]);
            p0[2] = fma2(wB.x, xx0, p0[2]); p0[3] = fma2(wB.y, xx0, p0[3]);
            p1[0] = fma2(wA.x, xx1, p1[0]); p1[1] = fma2(wA.y, xx1, p1[1]);
            p1[2] = fma2(wB.x, xx1, p1[2]); p1[3] = fma2(wB.y, xx1, p1[3]);
        }

        if (MODE == 0) {
            #pragma unroll
            for (int t = 0; t < 4; t++) {
                acc0[t] = add2(acc0[t], p0[t]);
                acc1[t] = add2(acc1[t], p1[t]);
            }
        } else {
            u64 d0 = 0ull, d1 = 0ull;
            #pragma unroll
            for (int t = 0; t < 4; t++) {
                d0 = fma2(p0[t], ov0[t], d0);
                d1 = fma2(p1[t], ov1[t], d1);
            }
            float lo, hi;
            unpack2(d0, lo, hi); float del0 = lo + hi;
            unpack2(d1, lo, hi); float del1 = lo + hi;
            del0 += __shfl_xor_sync(0xffffffffu, del0, 16);
            del1 += __shfl_xor_sync(0xffffffffu, del1, 16);
            del0 = fminf(del0, 70.0f); del1 = fminf(del1, 70.0f);
            float w0 = __expf(del0), w1 = __expf(del1);
            accw0 += w0; accw1 += w1;
            u64 w20 = pack2(w0, w0), w21 = pack2(w1, w1);
            #pragma unroll
            for (int t = 0; t < 4; t++) {
                acc0[t] = fma2(p0[t], w20, acc0[t]);
                acc1[t] = fma2(p1[t], w21, acc1[t]);
            }
        }
    }

    // partials -> smem
    {
        float2* s0 = reinterpret_cast<float2*>(&sredP[rgroup][b0][oh * 8]);
        float2* s1 = reinterpret_cast<float2*>(&sredP[rgroup][b1][oh * 8]);
        #pragma unroll
        for (int t = 0; t < 4; t++) {
            float lo, hi;
            unpack2(acc0[t], lo, hi); s0[t] = make_float2(lo, hi);
            unpack2(acc1[t], lo, hi); s1[t] = make_float2(lo, hi);
        }
        if (MODE != 0 && oh == 0) { sredW[rgroup][b0] = accw0; sredW[rgroup][b1] = accw1; }
    }
    __syncthreads();

    // fold 3 rgroups -> global atomics
    for (int idx = tid; idx < B_DIM * 16; idx += 192) {
        const int bb = idx >> 4, o = idx & 15;
        float v = sredP[0][bb][o] + sredP[1][bb][o] + sredP[2][bb][o];
        atomicAdd(&g_acc[c * (B_DIM * 16) + idx], v);
    }
    if (MODE != 0 && tid < B_DIM) {
        float v = sredW[0][tid] + sredW[1][tid] + sredW[2][tid];
        atomicAdd(&g_accw[c * B_DIM + tid], v);
    }

    // ---- last CTA: squash inline ----
    __threadfence();
    if (tid == 0) s_rank = atomicAdd(&g_ctr, 1);
    __syncthreads();
    if (s_rank == NCTAS - 1) {
        for (int pair = tid; pair < C_DIM * B_DIM; pair += 192) {
            const float* a = g_acc + pair * 16;
            float invw = (MODE == 0) ? (1.0f / (float)R_DIM) : (1.0f / __ldcg(&g_accw[pair]));
            float s[16], sq = 0.0f;
            #pragma unroll
            for (int o = 0; o < 16; o++) { s[o] = __ldcg(a + o) * invw; sq += s[o] * s[o]; }
            float coef = sq / ((1.0f + sq) * sqrtf(sq));
            float* dst = (MODE == 2) ? (dout + pair * 16) : (g_out[MODE] + pair * 16);
            #pragma unroll
            for (int o = 0; o < 16; o++) dst[o] = coef * s[o];
        }
        __syncthreads();
        for (int idx = tid; idx < C_DIM * B_DIM * 16; idx += 192) g_acc[idx] = 0.0f;
        for (int idx = tid; idx < C_DIM * B_DIM; idx += 192) g_accw[idx] = 0.0f;
        if (tid == 0) g_ctr = 0;
    }
}

extern "C" void kernel_launch(void* const* d_in, const int* in_sizes, int n_in,
                              void* d_out, int out_size) {
    const float* x = (const float*)d_in[0];          // [64, 6912, 8]
    const float* W = (const float*)d_in[1];          // [10, 6912, 8, 16]
    float* out = (float*)d_out;                      // [10, 64, 1, 1, 16]

    dim3 tgrid(R_DIM * 2 / 32, B_DIM / 32);          // (432, 2)
    k_transpose<<<tgrid, dim3(32, 8)>>>(reinterpret_cast<const float4*>(x));

    dim3 grid(R_DIM / R_BLK, C_DIM);                 // (144, 10)
    k_pass<0><<<grid, 192>>>(W, nullptr);
    k_pass<1><<<grid, 192>>>(W, nullptr);
    k_pass<2><<<grid, 192>>>(W, out);
}